// round 11
// baseline (speedup 1.0000x reference)
#include <cuda_runtime.h>
#include <math.h>
#include <stdint.h>

#define Bn   16
#define Tn   2048
#define Dn   512
#define G4n  2048          // 4*D
#define NBLK 128           // persistent blocks (<=148 SMs -> co-resident)
#define PADK 516           // padded row stride (floats); 516*4B=2064, 16B-aligned

// ---------------- device-global scratch (no runtime allocation) ------------
__device__ float g_xg[(size_t)Bn * Tn * G4n];   // 256 MB: xg for current layer
__device__ float g_y1[(size_t)Bn * Tn * Dn];    // 64 MB: layer-1 output seq
__device__ float g_hbuf[2][Bn * Dn];            // double-buffered h, [b][d]
__device__ unsigned int g_flags[NBLK];          // per-block step counters
__device__ unsigned int          g_bar_count;
__device__ volatile unsigned int g_bar_gen;

// ---------------- rare full grid barrier (prologue/epilogue only) ----------
__device__ __forceinline__ void grid_barrier() {
    __syncthreads();
    if (threadIdx.x == 0) {
        unsigned int g = g_bar_gen;
        __threadfence();
        if (atomicAdd(&g_bar_count, 1u) == (unsigned)gridDim.x - 1u) {
            g_bar_count = 0;
            __threadfence();
            g_bar_gen = g + 1;
        } else {
            while (g_bar_gen == g) { }
        }
        __threadfence();
    }
    __syncthreads();
}

// ---------------- release/acquire flag ops ----------------------------------
__device__ __forceinline__ void st_release_u32(unsigned int* p, unsigned int v) {
    asm volatile("st.release.gpu.global.u32 [%0], %1;" :: "l"(p), "r"(v) : "memory");
}
__device__ __forceinline__ unsigned int ld_acquire_u32(const unsigned int* p) {
    unsigned int v;
    asm volatile("ld.acquire.gpu.global.u32 %0, [%1];" : "=r"(v) : "l"(p) : "memory");
    return v;
}

// ---------------- packed fp32x2 helpers (sm_103a FFMA2, PTX-only) ----------
__device__ __forceinline__ void ffma2(unsigned long long& d,
                                      unsigned long long a,
                                      unsigned long long b) {
    asm("fma.rn.f32x2 %0, %1, %2, %0;" : "+l"(d) : "l"(a), "l"(b));
}
__device__ __forceinline__ unsigned long long pack2(float lo, float hi) {
    unsigned long long r;
    asm("mov.b64 %0, {%1, %2};" : "=l"(r) : "f"(lo), "f"(hi));
    return r;
}
__device__ __forceinline__ void unpack2(unsigned long long v, float& lo, float& hi) {
    asm("mov.b64 {%0, %1}, %2;" : "=f"(lo), "=f"(hi) : "l"(v));
}
__device__ __forceinline__ float fsum2(unsigned long long v) {
    float lo, hi; unpack2(v, lo, hi); return lo + hi;
}

__device__ __forceinline__ float fsig(float x) {
    return 1.0f / (1.0f + __expf(-x));
}
__device__ __forceinline__ float ftanh_(float x) {
    return 2.0f / (1.0f + __expf(-2.0f * x)) - 1.0f;
}

// ============================================================================
// SGEMM + bias: C[M=32768, N=2048] = A[M,512] @ W[512,2048] + bias
// 128x128 tile, 256 threads, 8x8 microtile, BK=8, fp32x2 packed FMA.
// acc2[p][j]: row pair (2p, 2p+1) of the 8 microtile rows, column j.
// ============================================================================
__global__ void __launch_bounds__(256, 2) gemm_bias_kernel(
    const float* __restrict__ A,
    const float* __restrict__ W,
    const float* __restrict__ bias,
    float* __restrict__ C)
{
    const int K = Dn, N = G4n;
    __shared__ __align__(16) float As[8][132];   // transposed [k][m]
    __shared__ __align__(16) float Bs[8][128];   // [k][n]

    const int tid  = threadIdx.x;
    const int bm   = blockIdx.y << 7;
    const int bn   = blockIdx.x << 7;
    const int arow = tid >> 1, acol = (tid & 1) << 2;
    const int brow = tid >> 5, bcol = (tid & 31) << 2;
    const int tr   = (tid >> 4) << 2;
    const int tc   = (tid & 15) << 2;

    unsigned long long acc2[4][8];
#pragma unroll
    for (int p = 0; p < 4; ++p)
#pragma unroll
        for (int j = 0; j < 8; ++j) acc2[p][j] = 0ull;

    float4 areg = *reinterpret_cast<const float4*>(&A[(size_t)(bm + arow) * K + acol]);
    float4 breg = *reinterpret_cast<const float4*>(&W[(size_t)brow * N + bn + bcol]);

#pragma unroll 1
    for (int k0 = 0; k0 < K; k0 += 8) {
        As[acol + 0][arow] = areg.x;
        As[acol + 1][arow] = areg.y;
        As[acol + 2][arow] = areg.z;
        As[acol + 3][arow] = areg.w;
        *reinterpret_cast<float4*>(&Bs[brow][bcol]) = breg;
        __syncthreads();

        if (k0 + 8 < K) {
            areg = *reinterpret_cast<const float4*>(&A[(size_t)(bm + arow) * K + (k0 + 8) + acol]);
            breg = *reinterpret_cast<const float4*>(&W[(size_t)(k0 + 8 + brow) * N + bn + bcol]);
        }

#pragma unroll
        for (int kk = 0; kk < 8; ++kk) {
            float4 a0 = *reinterpret_cast<const float4*>(&As[kk][tr]);
            float4 a1 = *reinterpret_cast<const float4*>(&As[kk][tr + 64]);
            float4 b0 = *reinterpret_cast<const float4*>(&Bs[kk][tc]);
            float4 b1 = *reinterpret_cast<const float4*>(&Bs[kk][tc + 64]);
            unsigned long long ap[4] = {
                pack2(a0.x, a0.y), pack2(a0.z, a0.w),
                pack2(a1.x, a1.y), pack2(a1.z, a1.w)
            };
            float bv[8] = {b0.x, b0.y, b0.z, b0.w, b1.x, b1.y, b1.z, b1.w};
#pragma unroll
            for (int j = 0; j < 8; ++j) {
                unsigned long long bd = pack2(bv[j], bv[j]);
                ffma2(acc2[0][j], ap[0], bd);
                ffma2(acc2[1][j], ap[1], bd);
                ffma2(acc2[2][j], ap[2], bd);
                ffma2(acc2[3][j], ap[3], bd);
            }
        }
        __syncthreads();
    }

    float4 bi0 = *reinterpret_cast<const float4*>(&bias[bn + tc]);
    float4 bi1 = *reinterpret_cast<const float4*>(&bias[bn + tc + 64]);
    float bvv[8] = {bi0.x, bi0.y, bi0.z, bi0.w, bi1.x, bi1.y, bi1.z, bi1.w};

#pragma unroll
    for (int p = 0; p < 4; ++p) {
        float rlo[8], rhi[8];
#pragma unroll
        for (int j = 0; j < 8; ++j) unpack2(acc2[p][j], rlo[j], rhi[j]);
        int i0   = 2 * p;                       // logical microtile row of lo
        int r_lo = bm + ((i0 < 4) ? (tr + i0) : (64 + tr + i0 - 4));
        int r_hi = r_lo + 1;                    // pair stays in same half
        float4 o;
        o = make_float4(rlo[0] + bvv[0], rlo[1] + bvv[1], rlo[2] + bvv[2], rlo[3] + bvv[3]);
        *reinterpret_cast<float4*>(&C[(size_t)r_lo * N + bn + tc]) = o;
        o = make_float4(rlo[4] + bvv[4], rlo[5] + bvv[5], rlo[6] + bvv[6], rlo[7] + bvv[7]);
        *reinterpret_cast<float4*>(&C[(size_t)r_lo * N + bn + tc + 64]) = o;
        o = make_float4(rhi[0] + bvv[0], rhi[1] + bvv[1], rhi[2] + bvv[2], rhi[3] + bvv[3]);
        *reinterpret_cast<float4*>(&C[(size_t)r_hi * N + bn + tc]) = o;
        o = make_float4(rhi[4] + bvv[4], rhi[5] + bvv[5], rhi[6] + bvv[6], rhi[7] + bvv[7]);
        *reinterpret_cast<float4*>(&C[(size_t)r_hi * N + bn + tc + 64]) = o;
    }
}

// ============================================================================
// Persistent LSTM recurrence, one layer. 128 blocks x 256 threads.
// Block bk owns h-cols d = 4bk+m (m=0..3) => 16 gate cols:
//   gcol(c) = (c>>2)*512 + bk*4 + (c&3),  c = 0..15.
// Wh slice SMEM-resident; c-state SMEM; h via L2 double buffer.
// Per-step sync: distributed flag barrier (st.release / ld.acquire),
// fused with h publication. g_flags[bk] = #steps completed by block bk.
// ============================================================================
__global__ void __launch_bounds__(256, 1) lstm_recur_kernel(
    const float* __restrict__ Wh,    // [512][2048], this layer
    const float* __restrict__ xg,    // g_xg
    float* __restrict__ yout,        // g_y1 or d_out
    const float* __restrict__ xres)  // nullptr, or x (residual, last layer)
{
    extern __shared__ float sm[];
    float* W_s  = sm;                 // [16][PADK]  W_s[c][k]
    float* H_s  = sm + 16 * PADK;     // [16][PADK]  H_s[b][k]
    float* psum = sm + 32 * PADK;     // [2][16][16] partials per k-half
    float* gbuf = psum + 512;         // [16][16]    gates [b][c]
    float* cbuf = gbuf + 256;         // [64]        c-state [b][m]

    const int tid = threadIdx.x;
    const int bk  = blockIdx.x;

    // ---- prologue: Wh slice -> SMEM, zero c and both h buffers ------------
    for (int idx = tid; idx < 16 * Dn; idx += 256) {
        int c = idx >> 9, k = idx & 511;
        int gcol = ((c >> 2) << 9) + (bk << 2) + (c & 3);
        W_s[c * PADK + k] = Wh[(size_t)k * G4n + gcol];
    }
    if (tid < 64) {
        cbuf[tid] = 0.0f;
        int m = tid & 3, b = tid >> 2;
        int d = (bk << 2) + m;
        g_hbuf[0][b * Dn + d] = 0.0f;
        g_hbuf[1][b * Dn + d] = 0.0f;
        __threadfence();
    }
    grid_barrier();

    // compute-phase ids
    const int lane = tid & 31, warp = tid >> 5;
    const int clo = lane & 7,  b1q = lane >> 3;
    const int kh  = warp >> 2, chi = (warp >> 1) & 1, b1h = warp & 1;
    const int cc  = clo + (chi << 3);          // 0..15
    const int b1  = b1q + (b1h << 2);          // 0..7
    const int b2  = b1 + 8;
    const float4* Wf4  = reinterpret_cast<const float4*>(W_s + cc * PADK + kh * 256);
    const float4* H1f4 = reinterpret_cast<const float4*>(H_s + b1 * PADK + kh * 256);
    const float4* H2f4 = reinterpret_cast<const float4*>(H_s + b2 * PADK + kh * 256);

    // finishing-phase ids (one output per thread)
    const int fb = tid >> 4, fc = tid & 15;
    const int fgc = ((fc >> 2) << 9) + (bk << 2) + (fc & 3);
    // gate-phase ids
    const int gm = tid & 3, gb = tid >> 2;
    const int gd = (bk << 2) + gm;

    for (int t = 0; t < Tn; ++t) {
        // 0. wait until every block has published h(t-1)  (t=0: trivially true)
        if (tid < NBLK) {
            while (ld_acquire_u32(&g_flags[tid]) < (unsigned)t) { }
        }
        __syncthreads();

        // 1. h(t-1): global double buffer -> SMEM ([b][k], row pad PADK)
        const float4* hb = reinterpret_cast<const float4*>(g_hbuf[(t + 1) & 1]);
#pragma unroll
        for (int j = 0; j < 8; ++j) {
            int idx = j * 256 + tid;           // 0..2047 float4
            int b   = idx >> 7, k4 = idx & 127;
            float4 v = __ldcg(hb + idx);
            *reinterpret_cast<float4*>(H_s + b * PADK + (k4 << 2)) = v;
        }
        // 2. prefetch xg (finishing layout) + residual (gate layout)
        float xv = __ldg(&xg[((size_t)fb * Tn + t) * G4n + fgc]);
        float xrv = 0.0f;
        if (xres != nullptr && tid < 64)
            xrv = __ldg(&xres[((size_t)gb * Tn + t) * Dn + gd]);

        __syncthreads();   // H_s ready

        // 3. half-k dot products, fp32x2 packed over (k,k+1)
        unsigned long long a0 = 0ull, a1 = 0ull, e0 = 0ull, e1 = 0ull;
#pragma unroll 8
        for (int i = 0; i < 64; ++i) {          // 64 x float4 = 256 floats
            float4 w  = Wf4[i];
            float4 h1 = H1f4[i];
            float4 h2 = H2f4[i];
            unsigned long long wlo = pack2(w.x, w.y), whi = pack2(w.z, w.w);
            ffma2(a0, wlo, pack2(h1.x, h1.y));
            ffma2(a1, whi, pack2(h1.z, h1.w));
            ffma2(e0, wlo, pack2(h2.x, h2.y));
            ffma2(e1, whi, pack2(h2.z, h2.w));
        }
        psum[(kh << 8) + b1 * 16 + cc] = fsum2(a0) + fsum2(a1);
        psum[(kh << 8) + b2 * 16 + cc] = fsum2(e0) + fsum2(e1);
        __syncthreads();

        // 4. combine k-halves + xg -> gates buffer
        gbuf[tid] = xv + psum[tid] + psum[256 + tid];
        __syncthreads();

        // 5. gate phase (warps 0-1 only): c,h update; publish h + flag.
        //    Other warps fall through to the next iteration's poll.
        if (tid < 64) {
            float gi = gbuf[gb * 16 + 0  + gm];
            float gf = gbuf[gb * 16 + 4  + gm];
            float gg = gbuf[gb * 16 + 8  + gm];
            float go = gbuf[gb * 16 + 12 + gm];
            float cn = fsig(gf) * cbuf[tid] + fsig(gi) * ftanh_(gg);
            float h  = fsig(go) * ftanh_(cn);
            cbuf[tid] = cn;
            __stcg(&g_hbuf[t & 1][gb * Dn + gd], h);
            // order the 64 h-stores (bar.sync gives CTA-scope hb edges),
            // then one release store publishes them at gpu scope
            asm volatile("bar.sync 1, 64;" ::: "memory");
            if (tid == 0) st_release_u32(&g_flags[bk], (unsigned)(t + 1));
            // off critical path: output sequence
            size_t yi = ((size_t)gb * Tn + t) * Dn + gd;
            yout[yi] = (xres != nullptr) ? (h + xrv) : h;
        }
        // no full barrier here: next iteration's poll + __syncthreads covers it
    }

    // ---- epilogue: everyone done polling, then reset flags for next launch
    grid_barrier();
    if (tid == 0) g_flags[bk] = 0;
}

// ============================================================================
extern "C" void kernel_launch(void* const* d_in, const int* in_sizes, int n_in,
                              void* d_out, int out_size) {
    const float* x  = (const float*)d_in[0];   // [16,2048,512]
    const float* Wx = (const float*)d_in[1];   // [2,512,2048]
    const float* Wh = (const float*)d_in[2];   // [2,512,2048]
    const float* bb = (const float*)d_in[3];   // [2,2048]
    float* out = (float*)d_out;                // [16,2048,512]

    float *xg_p, *y1_p;
    cudaGetSymbolAddress((void**)&xg_p, g_xg);
    cudaGetSymbolAddress((void**)&y1_p, g_y1);

    const int smem = (32 * PADK + 512 + 256 + 64) * (int)sizeof(float); // ~69.3 KB
    cudaFuncSetAttribute(lstm_recur_kernel,
                         cudaFuncAttributeMaxDynamicSharedMemorySize, smem);

    dim3 ggrid(G4n / 128, (Bn * Tn) / 128);    // 16 x 256

    // ----- layer 0 -----
    gemm_bias_kernel<<<ggrid, 256>>>(x, Wx, bb, xg_p);
    lstm_recur_kernel<<<NBLK, 256, smem>>>(Wh, xg_p, y1_p, nullptr);

    // ----- layer 1 (+ residual) -----
    gemm_bias_kernel<<<ggrid, 256>>>(y1_p, Wx + (size_t)Dn * G4n, bb + G4n, xg_p);
    lstm_recur_kernel<<<NBLK, 256, smem>>>(Wh + (size_t)Dn * G4n, xg_p, out, x);
}

// round 12
// speedup vs baseline: 2.1182x; 2.1182x over previous
#include <cuda_runtime.h>
#include <math.h>
#include <stdint.h>

#define Bn   16
#define Tn   2048
#define Dn   512
#define G4n  2048          // 4*D
#define NBLK 128           // persistent blocks (<=148 SMs -> co-resident)
#define PADK 516           // padded row stride (floats); 2064B, 16B-aligned

typedef unsigned long long ull;

// ---------------- device-global scratch (no runtime allocation) ------------
__device__ float g_xg[(size_t)Bn * Tn * G4n];   // 256 MB: xg for layer 0
__device__ float g_h0[2][Bn * Dn];              // layer-0 h, double buffered [b][d]
__device__ float g_h1[2][Bn * Dn];              // layer-1 h, double buffered
__device__ unsigned int g_round_arrive;         // monotonic round counter
__device__ unsigned int          g_bar_count;   // prologue/epilogue barrier
__device__ volatile unsigned int g_bar_gen;

// ---------------- rare full grid barrier (prologue/epilogue only) ----------
__device__ __forceinline__ void grid_barrier() {
    __syncthreads();
    if (threadIdx.x == 0) {
        unsigned int g = g_bar_gen;
        __threadfence();
        if (atomicAdd(&g_bar_count, 1u) == (unsigned)gridDim.x - 1u) {
            g_bar_count = 0;
            __threadfence();
            g_bar_gen = g + 1;
        } else {
            while (g_bar_gen == g) { }
        }
        __threadfence();
    }
    __syncthreads();
}

// ---------------- round-barrier primitives ----------------------------------
__device__ __forceinline__ void red_release_add(unsigned int* p, unsigned int v) {
    asm volatile("red.release.gpu.global.add.u32 [%0], %1;" :: "l"(p), "r"(v) : "memory");
}
__device__ __forceinline__ unsigned int ld_acquire_u32(const unsigned int* p) {
    unsigned int v;
    asm volatile("ld.acquire.gpu.global.u32 %0, [%1];" : "=r"(v) : "l"(p) : "memory");
    return v;
}

// ---------------- packed fp32x2 helpers (sm_103a FFMA2, PTX-only) ----------
__device__ __forceinline__ void ffma2(ull& d, ull a, ull b) {
    asm("fma.rn.f32x2 %0, %1, %2, %0;" : "+l"(d) : "l"(a), "l"(b));
}
__device__ __forceinline__ ull pack2(float lo, float hi) {
    ull r;
    asm("mov.b64 %0, {%1, %2};" : "=l"(r) : "f"(lo), "f"(hi));
    return r;
}
__device__ __forceinline__ void unpack2(ull v, float& lo, float& hi) {
    asm("mov.b64 {%0, %1}, %2;" : "=f"(lo), "=f"(hi) : "l"(v));
}
__device__ __forceinline__ float fsum2(ull v) {
    float lo, hi; unpack2(v, lo, hi); return lo + hi;
}

__device__ __forceinline__ float fsig(float x) {
    return 1.0f / (1.0f + __expf(-x));
}
__device__ __forceinline__ float ftanh_(float x) {
    return 2.0f / (1.0f + __expf(-2.0f * x)) - 1.0f;
}

// ============================================================================
// SGEMM + bias: C[M=32768, N=2048] = A[M,512] @ W[512,2048] + bias  (layer 0)
// 128x128 tile, 256 threads, 8x8 microtile, BK=8, fp32x2 packed FMA.
// ============================================================================
__global__ void __launch_bounds__(256, 2) gemm_bias_kernel(
    const float* __restrict__ A,
    const float* __restrict__ W,
    const float* __restrict__ bias,
    float* __restrict__ C)
{
    const int K = Dn, N = G4n;
    __shared__ __align__(16) float As[8][132];   // transposed [k][m]
    __shared__ __align__(16) float Bs[8][128];   // [k][n]

    const int tid  = threadIdx.x;
    const int bm   = blockIdx.y << 7;
    const int bn   = blockIdx.x << 7;
    const int arow = tid >> 1, acol = (tid & 1) << 2;
    const int brow = tid >> 5, bcol = (tid & 31) << 2;
    const int tr   = (tid >> 4) << 2;
    const int tc   = (tid & 15) << 2;

    ull acc2[4][8];
#pragma unroll
    for (int p = 0; p < 4; ++p)
#pragma unroll
        for (int j = 0; j < 8; ++j) acc2[p][j] = 0ull;

    float4 areg = *reinterpret_cast<const float4*>(&A[(size_t)(bm + arow) * K + acol]);
    float4 breg = *reinterpret_cast<const float4*>(&W[(size_t)brow * N + bn + bcol]);

#pragma unroll 1
    for (int k0 = 0; k0 < K; k0 += 8) {
        As[acol + 0][arow] = areg.x;
        As[acol + 1][arow] = areg.y;
        As[acol + 2][arow] = areg.z;
        As[acol + 3][arow] = areg.w;
        *reinterpret_cast<float4*>(&Bs[brow][bcol]) = breg;
        __syncthreads();

        if (k0 + 8 < K) {
            areg = *reinterpret_cast<const float4*>(&A[(size_t)(bm + arow) * K + (k0 + 8) + acol]);
            breg = *reinterpret_cast<const float4*>(&W[(size_t)(k0 + 8 + brow) * N + bn + bcol]);
        }

#pragma unroll
        for (int kk = 0; kk < 8; ++kk) {
            float4 a0 = *reinterpret_cast<const float4*>(&As[kk][tr]);
            float4 a1 = *reinterpret_cast<const float4*>(&As[kk][tr + 64]);
            float4 b0 = *reinterpret_cast<const float4*>(&Bs[kk][tc]);
            float4 b1 = *reinterpret_cast<const float4*>(&Bs[kk][tc + 64]);
            ull ap[4] = { pack2(a0.x, a0.y), pack2(a0.z, a0.w),
                          pack2(a1.x, a1.y), pack2(a1.z, a1.w) };
            float bv[8] = {b0.x, b0.y, b0.z, b0.w, b1.x, b1.y, b1.z, b1.w};
#pragma unroll
            for (int j = 0; j < 8; ++j) {
                ull bd = pack2(bv[j], bv[j]);
                ffma2(acc2[0][j], ap[0], bd);
                ffma2(acc2[1][j], ap[1], bd);
                ffma2(acc2[2][j], ap[2], bd);
                ffma2(acc2[3][j], ap[3], bd);
            }
        }
        __syncthreads();
    }

    float4 bi0 = *reinterpret_cast<const float4*>(&bias[bn + tc]);
    float4 bi1 = *reinterpret_cast<const float4*>(&bias[bn + tc + 64]);
    float bvv[8] = {bi0.x, bi0.y, bi0.z, bi0.w, bi1.x, bi1.y, bi1.z, bi1.w};

#pragma unroll
    for (int p = 0; p < 4; ++p) {
        float rlo[8], rhi[8];
#pragma unroll
        for (int j = 0; j < 8; ++j) unpack2(acc2[p][j], rlo[j], rhi[j]);
        int i0   = 2 * p;
        int r_lo = bm + ((i0 < 4) ? (tr + i0) : (64 + tr + i0 - 4));
        int r_hi = r_lo + 1;
        float4 o;
        o = make_float4(rlo[0] + bvv[0], rlo[1] + bvv[1], rlo[2] + bvv[2], rlo[3] + bvv[3]);
        *reinterpret_cast<float4*>(&C[(size_t)r_lo * N + bn + tc]) = o;
        o = make_float4(rlo[4] + bvv[4], rlo[5] + bvv[5], rlo[6] + bvv[6], rlo[7] + bvv[7]);
        *reinterpret_cast<float4*>(&C[(size_t)r_lo * N + bn + tc + 64]) = o;
        o = make_float4(rhi[0] + bvv[0], rhi[1] + bvv[1], rhi[2] + bvv[2], rhi[3] + bvv[3]);
        *reinterpret_cast<float4*>(&C[(size_t)r_hi * N + bn + tc]) = o;
        o = make_float4(rhi[4] + bvv[4], rhi[5] + bvv[5], rhi[6] + bvv[6], rhi[7] + bvv[7]);
        *reinterpret_cast<float4*>(&C[(size_t)r_hi * N + bn + tc + 64]) = o;
    }
}

// ============================================================================
// Fused two-layer wavefront LSTM. 128 blocks x 256 threads, persistent.
// Round r (0..Tn): layer-0 computes t=r (r<Tn), layer-1 computes t=r-1 (r>=1).
// Block bk owns h-cols d=4bk+m (m=0..3) FOR BOTH LAYERS => 16 gate cols/layer.
// Layer-1 gate = h0(t) @ Wx1 + h1(t-1) @ Wh1 + b1   (no separate GEMM).
// SMEM: Wh0 / Wx1 / Wh1 slices (resident), H0/H1 round buffers, psum/gates/c.
// Sync: one red.release arrival per block; tid0-only acquire poll of target 128*r.
// ============================================================================
__global__ void __launch_bounds__(256, 1) lstm_fused_kernel(
    const float* __restrict__ Wh0,
    const float* __restrict__ Wx1,
    const float* __restrict__ Wh1,
    const float* __restrict__ bias1,   // [2048] layer-1 bias
    const float* __restrict__ xg0,     // g_xg (layer-0 input gates, bias added)
    const float* __restrict__ x,       // residual input [16,2048,512]
    float* __restrict__ out)           // [16,2048,512]
{
    extern __shared__ float sm[];
    float* W0  = sm;                   // [16][PADK]
    float* W1x = sm + 16 * PADK;       // [16][PADK]
    float* W1h = sm + 32 * PADK;       // [16][PADK]
    float* H0  = sm + 48 * PADK;       // [16][PADK]
    float* H1  = sm + 64 * PADK;       // [16][PADK]
    float* psum = sm + 80 * PADK;      // [3][2][16][16] = 1536
    float* gbuf = psum + 1536;         // [2][16][16]    = 512
    float* cbuf = gbuf + 512;          // [128] c-state: [L][b][m]
    float* b1s  = cbuf + 128;          // [16] layer-1 bias slice

    const int tid = threadIdx.x;
    const int bk  = blockIdx.x;

    // ---- prologue: W slices -> SMEM, bias, zero c / h buffers -------------
    for (int idx = tid; idx < 3 * 16 * Dn; idx += 256) {
        int s = idx >> 13;                 // 8192 per slice
        int rm = idx & 8191;
        int c = rm >> 9, k = rm & 511;
        int gcol = ((c >> 2) << 9) + (bk << 2) + (c & 3);
        const float* src = (s == 0) ? Wh0 : ((s == 1) ? Wx1 : Wh1);
        sm[s * 16 * PADK + c * PADK + k] = src[(size_t)k * G4n + gcol];
    }
    if (tid < 16)
        b1s[tid] = bias1[((tid >> 2) << 9) + (bk << 2) + (tid & 3)];
    if (tid < 128) cbuf[tid] = 0.0f;
    {   // zero both parities of both h buffers for owned columns
        int par = tid >> 7, L = (tid >> 6) & 1, s = tid & 63;
        int b = s >> 2, m = s & 3, d = (bk << 2) + m;
        float* dst = L ? g_h1[par] : g_h0[par];
        dst[b * Dn + d] = 0.0f;
    }
    __threadfence();
    grid_barrier();

    // ---- compute-phase ids -------------------------------------------------
    const int lane = tid & 31, warp = tid >> 5;
    const int clo = lane & 7,  b1q = lane >> 3;
    const int kh  = warp >> 2, chi = (warp >> 1) & 1, b1h = warp & 1;
    const int cc  = clo + (chi << 3);          // 0..15
    const int b1  = b1q + (b1h << 2);          // 0..7
    const int b2  = b1 + 8;
    const ulonglong2* W0p  = reinterpret_cast<const ulonglong2*>(W0  + cc * PADK + kh * 256);
    const ulonglong2* W1xp = reinterpret_cast<const ulonglong2*>(W1x + cc * PADK + kh * 256);
    const ulonglong2* W1hp = reinterpret_cast<const ulonglong2*>(W1h + cc * PADK + kh * 256);
    const ulonglong2* H0a  = reinterpret_cast<const ulonglong2*>(H0 + b1 * PADK + kh * 256);
    const ulonglong2* H0b  = reinterpret_cast<const ulonglong2*>(H0 + b2 * PADK + kh * 256);
    const ulonglong2* H1a  = reinterpret_cast<const ulonglong2*>(H1 + b1 * PADK + kh * 256);
    const ulonglong2* H1b  = reinterpret_cast<const ulonglong2*>(H1 + b2 * PADK + kh * 256);

    // reduce-phase ids (one (b,c) pair per thread, both layers)
    const int fb = tid >> 4, fc = tid & 15;
    const int fgc = ((fc >> 2) << 9) + (bk << 2) + (fc & 3);
    // gate-phase ids (tid < 128): L, b, m
    const int gL = tid >> 6, gs = tid & 63;
    const int gb = gs >> 2, gm = gs & 3;
    const int gd = (bk << 2) + gm;

#pragma unroll 1
    for (int r = 0; r <= Tn; ++r) {
        // 0. wait for round r inputs (published at end of round r-1)
        if (r > 0) {
            if (tid == 0) {
                unsigned int target = 128u * (unsigned)r;
                while (ld_acquire_u32(&g_round_arrive) < target) { }
            }
            __syncthreads();
        }

        // 1. broadcast copies: h0(r-1), h1(r-2) -> SMEM
        const float4* s0 = reinterpret_cast<const float4*>(g_h0[(r + 1) & 1]);
        const float4* s1 = reinterpret_cast<const float4*>(g_h1[(r + 1) & 1]);
#pragma unroll
        for (int j = 0; j < 8; ++j) {
            int idx = j * 256 + tid;            // 0..2047 float4
            int b = idx >> 7, k4 = idx & 127;
            float4 v0 = __ldcg(s0 + idx);
            float4 v1 = __ldcg(s1 + idx);
            *reinterpret_cast<float4*>(H0 + b * PADK + (k4 << 2)) = v0;
            *reinterpret_cast<float4*>(H1 + b * PADK + (k4 << 2)) = v1;
        }
        // 2. prefetches: xg0 (layer-0 reduce), x residual (layer-1 gate)
        float xv = 0.0f;
        if (r < Tn) xv = __ldg(&xg0[((size_t)fb * Tn + r) * G4n + fgc]);
        float xrv = 0.0f;
        if (gL == 1 && tid < 128 && r >= 1)
            xrv = __ldg(&x[((size_t)gb * Tn + (r - 1)) * Dn + gd]);

        __syncthreads();   // H0/H1 ready

        // 3a. fused segments 0+1: (Wh0, Wx1) x h0, two batches each
        ull a00 = 0, a01 = 0, a10 = 0, a11 = 0;   // seg0: b1, b2
        ull s00 = 0, s01 = 0, s10 = 0, s11 = 0;   // seg1: b1, b2
#pragma unroll 8
        for (int i = 0; i < 64; ++i) {
            ulonglong2 w0 = W0p[i];
            ulonglong2 w1 = W1xp[i];
            ulonglong2 ha = H0a[i];
            ulonglong2 hb = H0b[i];
            ffma2(a00, w0.x, ha.x); ffma2(a01, w0.y, ha.y);
            ffma2(a10, w0.x, hb.x); ffma2(a11, w0.y, hb.y);
            ffma2(s00, w1.x, ha.x); ffma2(s01, w1.y, ha.y);
            ffma2(s10, w1.x, hb.x); ffma2(s11, w1.y, hb.y);
        }
        // 3b. segment 2: Wh1 x h1
        ull t00 = 0, t01 = 0, t10 = 0, t11 = 0;
#pragma unroll 8
        for (int i = 0; i < 64; ++i) {
            ulonglong2 w  = W1hp[i];
            ulonglong2 ha = H1a[i];
            ulonglong2 hb = H1b[i];
            ffma2(t00, w.x, ha.x); ffma2(t01, w.y, ha.y);
            ffma2(t10, w.x, hb.x); ffma2(t11, w.y, hb.y);
        }
        // psum[seg][kh][b][c]
        psum[((0 * 2 + kh) * 16 + b1) * 16 + cc] = fsum2(a00) + fsum2(a01);
        psum[((0 * 2 + kh) * 16 + b2) * 16 + cc] = fsum2(a10) + fsum2(a11);
        psum[((1 * 2 + kh) * 16 + b1) * 16 + cc] = fsum2(s00) + fsum2(s01);
        psum[((1 * 2 + kh) * 16 + b2) * 16 + cc] = fsum2(s10) + fsum2(s11);
        psum[((2 * 2 + kh) * 16 + b1) * 16 + cc] = fsum2(t00) + fsum2(t01);
        psum[((2 * 2 + kh) * 16 + b2) * 16 + cc] = fsum2(t10) + fsum2(t11);
        __syncthreads();

        // 4. reduce k-halves -> gate pre-activations, both layers
        {
            int o = fb * 16 + fc;
            float g0 = xv + psum[o] + psum[256 + o];
            float g1 = b1s[fc] + psum[512 + o] + psum[768 + o]
                                + psum[1024 + o] + psum[1280 + o];
            gbuf[o]       = g0;
            gbuf[256 + o] = g1;
        }
        __syncthreads();

        // 5. gate phase: 128 threads, one (L,b,m) each
        if (tid < 128) {
            bool active = (gL == 0) ? (r < Tn) : (r >= 1);
            if (active) {
                const float* gp = gbuf + gL * 256 + gb * 16;
                float gi = gp[0  + gm];
                float gf = gp[4  + gm];
                float gg = gp[8  + gm];
                float go = gp[12 + gm];
                float cn = fsig(gf) * cbuf[tid] + fsig(gi) * ftanh_(gg);
                float h  = fsig(go) * ftanh_(cn);
                cbuf[tid] = cn;
                float* dst = gL ? g_h1[r & 1] : g_h0[r & 1];
                __stcg(&dst[gb * Dn + gd], h);
                if (gL == 1)
                    out[((size_t)gb * Tn + (r - 1)) * Dn + gd] = h + xrv;
            }
        }
        __syncthreads();   // order h stores (CTA scope) before release arrival
        if (tid == 0) red_release_add(&g_round_arrive, 1u);
    }

    // ---- epilogue: drain, then reset the round counter for the next launch
    grid_barrier();
    if (bk == 0 && tid == 0) g_round_arrive = 0u;
}

// ============================================================================
extern "C" void kernel_launch(void* const* d_in, const int* in_sizes, int n_in,
                              void* d_out, int out_size) {
    const float* x  = (const float*)d_in[0];   // [16,2048,512]
    const float* Wx = (const float*)d_in[1];   // [2,512,2048]
    const float* Wh = (const float*)d_in[2];   // [2,512,2048]
    const float* bb = (const float*)d_in[3];   // [2,2048]
    float* out = (float*)d_out;                // [16,2048,512]

    float* xg_p;
    cudaGetSymbolAddress((void**)&xg_p, g_xg);

    const int smem = (80 * PADK + 1536 + 512 + 128 + 16) * (int)sizeof(float); // ~174 KB
    cudaFuncSetAttribute(lstm_fused_kernel,
                         cudaFuncAttributeMaxDynamicSharedMemorySize, smem);

    dim3 ggrid(G4n / 128, (Bn * Tn) / 128);    // 16 x 256

    // layer-0 input GEMM (bias0 folded in)
    gemm_bias_kernel<<<ggrid, 256>>>(x, Wx, bb, xg_p);

    // fused two-layer wavefront recurrence (+ residual)
    lstm_fused_kernel<<<NBLK, 256, smem>>>(
        Wh,                        // Wh0
        Wx + (size_t)Dn * G4n,     // Wx1
        Wh + (size_t)Dn * G4n,     // Wh1
        bb + G4n,                  // bias1
        xg_p, x, out);
}